// round 1
// baseline (speedup 1.0000x reference)
#include <cuda_runtime.h>

#define B 16
#define L 2048
#define EPS 1e-8f

// scratch: s = cos(phi), r = sin(phi) per element
__device__ float g_s[B * L];
__device__ float g_r[B * L];

// Kernel 1: one block per batch row. min/max reduce, then compute s, r.
__global__ void gaf_prep_kernel(const float* __restrict__ x) {
    const int b = blockIdx.x;
    const float* row = x + b * L;
    const int tid = threadIdx.x;           // 256 threads, 8 elems each

    float vmin =  3.4e38f, vmax = -3.4e38f;
    #pragma unroll
    for (int k = 0; k < 8; k++) {
        float v = row[tid + k * 256];
        vmin = fminf(vmin, v);
        vmax = fmaxf(vmax, v);
    }

    __shared__ float smin[256], smax[256];
    smin[tid] = vmin; smax[tid] = vmax;
    __syncthreads();
    #pragma unroll
    for (int s = 128; s > 0; s >>= 1) {
        if (tid < s) {
            smin[tid] = fminf(smin[tid], smin[tid + s]);
            smax[tid] = fmaxf(smax[tid], smax[tid + s]);
        }
        __syncthreads();
    }
    const float mn = smin[0];
    const float inv = 2.0f / (smax[0] - mn + EPS);

    #pragma unroll
    for (int k = 0; k < 8; k++) {
        int idx = tid + k * 256;
        float s = (row[idx] - mn) * inv - 1.0f;
        s = fminf(fmaxf(s, -1.0f + EPS), 1.0f - EPS);
        g_s[b * L + idx] = s;
        g_r[b * L + idx] = sqrtf(fmaxf(1.0f - s * s, 0.0f));
    }
}

// Kernel 2: out[b][i][j] = s_i*s_j - r_i*r_j. One block per (i, b) row,
// 512 threads, float4 stores (2048 floats per block).
__global__ void __launch_bounds__(512) gaf_outer_kernel(float* __restrict__ out) {
    const int i = blockIdx.x;
    const int b = blockIdx.y;
    const int t = threadIdx.x;

    const float si = g_s[b * L + i];
    const float ri = g_r[b * L + i];

    const float4* sj = reinterpret_cast<const float4*>(g_s + b * L);
    const float4* rj = reinterpret_cast<const float4*>(g_r + b * L);
    float4 s4 = sj[t];
    float4 r4 = rj[t];

    float4 o;
    o.x = si * s4.x - ri * r4.x;
    o.y = si * s4.y - ri * r4.y;
    o.z = si * s4.z - ri * r4.z;
    o.w = si * s4.w - ri * r4.w;

    reinterpret_cast<float4*>(out + (size_t)b * L * L + (size_t)i * L)[t] = o;
}

extern "C" void kernel_launch(void* const* d_in, const int* in_sizes, int n_in,
                              void* d_out, int out_size) {
    const float* x = (const float*)d_in[0];
    float* out = (float*)d_out;

    gaf_prep_kernel<<<B, 256>>>(x);
    dim3 grid(L, B);
    gaf_outer_kernel<<<grid, 512>>>(out);
}

// round 2
// speedup vs baseline: 1.1476x; 1.1476x over previous
#include <cuda_runtime.h>

#define B 16
#define L 2048
#define EPS 1e-8f
#define ROWS_PER_BLK 8

// scratch: s = cos(phi), r = sin(phi) per element
__device__ float g_s[B * L];
__device__ float g_r[B * L];

// Kernel 1: one block per batch row. min/max reduce, then compute s, r.
__global__ void gaf_prep_kernel(const float* __restrict__ x) {
    const int b = blockIdx.x;
    const float* row = x + b * L;
    const int tid = threadIdx.x;           // 256 threads, 8 elems each

    float vmin =  3.4e38f, vmax = -3.4e38f;
    #pragma unroll
    for (int k = 0; k < 8; k++) {
        float v = row[tid + k * 256];
        vmin = fminf(vmin, v);
        vmax = fmaxf(vmax, v);
    }

    __shared__ float smin[256], smax[256];
    smin[tid] = vmin; smax[tid] = vmax;
    __syncthreads();
    #pragma unroll
    for (int s = 128; s > 0; s >>= 1) {
        if (tid < s) {
            smin[tid] = fminf(smin[tid], smin[tid + s]);
            smax[tid] = fmaxf(smax[tid], smax[tid + s]);
        }
        __syncthreads();
    }
    const float mn = smin[0];
    const float inv = 2.0f / (smax[0] - mn + EPS);

    #pragma unroll
    for (int k = 0; k < 8; k++) {
        int idx = tid + k * 256;
        float s = (row[idx] - mn) * inv - 1.0f;
        s = fminf(fmaxf(s, -1.0f + EPS), 1.0f - EPS);
        g_s[b * L + idx] = s;
        g_r[b * L + idx] = sqrtf(fmaxf(1.0f - s * s, 0.0f));
    }
}

// Kernel 2: out[b][i][j] = s_i*s_j - r_i*r_j.
// One block = 8 consecutive i-rows of one batch. 256 threads.
// Each thread holds two float4 j-segments in registers (columns 4t..4t+3
// and 1024+4t..1024+4t+3), reused across all 8 rows. 16 independent
// STG.128 streaming stores per thread.
__global__ void __launch_bounds__(256) gaf_outer_kernel(float* __restrict__ out) {
    const int i0 = blockIdx.x * ROWS_PER_BLK;
    const int b  = blockIdx.y;
    const int t  = threadIdx.x;

    const float4* sj = reinterpret_cast<const float4*>(g_s + b * L);
    const float4* rj = reinterpret_cast<const float4*>(g_r + b * L);
    const float4 s_lo = sj[t];
    const float4 s_hi = sj[t + 256];
    const float4 r_lo = rj[t];
    const float4 r_hi = rj[t + 256];

    float si[ROWS_PER_BLK], ri[ROWS_PER_BLK];
    #pragma unroll
    for (int k = 0; k < ROWS_PER_BLK; k++) {
        si[k] = g_s[b * L + i0 + k];
        ri[k] = g_r[b * L + i0 + k];
    }

    float* base = out + (size_t)b * L * L + (size_t)i0 * L;

    #pragma unroll
    for (int k = 0; k < ROWS_PER_BLK; k++) {
        float4 o_lo, o_hi;
        o_lo.x = si[k] * s_lo.x - ri[k] * r_lo.x;
        o_lo.y = si[k] * s_lo.y - ri[k] * r_lo.y;
        o_lo.z = si[k] * s_lo.z - ri[k] * r_lo.z;
        o_lo.w = si[k] * s_lo.w - ri[k] * r_lo.w;
        o_hi.x = si[k] * s_hi.x - ri[k] * r_hi.x;
        o_hi.y = si[k] * s_hi.y - ri[k] * r_hi.y;
        o_hi.z = si[k] * s_hi.z - ri[k] * r_hi.z;
        o_hi.w = si[k] * s_hi.w - ri[k] * r_hi.w;

        float4* rowp = reinterpret_cast<float4*>(base + (size_t)k * L);
        __stcs(rowp + t, o_lo);
        __stcs(rowp + t + 256, o_hi);
    }
}

extern "C" void kernel_launch(void* const* d_in, const int* in_sizes, int n_in,
                              void* d_out, int out_size) {
    const float* x = (const float*)d_in[0];
    float* out = (float*)d_out;

    gaf_prep_kernel<<<B, 256>>>(x);
    dim3 grid(L / ROWS_PER_BLK, B);
    gaf_outer_kernel<<<grid, 256>>>(out);
}

// round 3
// speedup vs baseline: 1.1788x; 1.0272x over previous
#include <cuda_runtime.h>

#define B 16
#define L 2048
#define EPS 1e-8f
#define ROWS_PER_BLK 8
#define THREADS 512

// Fused: out[b][i][j] = s_i*s_j - r_i*r_j where s = clipped minmax-scaled x,
// r = sqrt(1-s^2). Each block recomputes the per-batch-row prep (min/max +
// s/r) into shared memory — x row is 8KB and L2-resident, the redundant
// reduction rides in idle issue slots. No second kernel, no dependency stall.
__global__ void __launch_bounds__(THREADS) gaf_fused_kernel(
    const float* __restrict__ x, float* __restrict__ out) {
    const int b  = blockIdx.y;
    const int i0 = blockIdx.x * ROWS_PER_BLK;
    const int t  = threadIdx.x;
    const int lane = t & 31;
    const int wid  = t >> 5;                 // 16 warps

    __shared__ float s_s[L];
    __shared__ float s_r[L];
    __shared__ float red_min[16], red_max[16];
    __shared__ float sh_mn, sh_inv;

    // ---- load x row: 512 threads x float4 = 2048 elems ----
    const float4 v = reinterpret_cast<const float4*>(x + b * L)[t];

    float vmin = fminf(fminf(v.x, v.y), fminf(v.z, v.w));
    float vmax = fmaxf(fmaxf(v.x, v.y), fmaxf(v.z, v.w));

    // warp reduce
    #pragma unroll
    for (int o = 16; o > 0; o >>= 1) {
        vmin = fminf(vmin, __shfl_xor_sync(0xffffffffu, vmin, o));
        vmax = fmaxf(vmax, __shfl_xor_sync(0xffffffffu, vmax, o));
    }
    if (lane == 0) { red_min[wid] = vmin; red_max[wid] = vmax; }
    __syncthreads();

    // final reduce over 16 warp results by warp 0
    if (wid == 0) {
        float m0 = (lane < 16) ? red_min[lane] :  3.4e38f;
        float m1 = (lane < 16) ? red_max[lane] : -3.4e38f;
        #pragma unroll
        for (int o = 8; o > 0; o >>= 1) {
            m0 = fminf(m0, __shfl_xor_sync(0xffffffffu, m0, o));
            m1 = fmaxf(m1, __shfl_xor_sync(0xffffffffu, m1, o));
        }
        if (lane == 0) {
            sh_mn  = m0;
            sh_inv = 2.0f / (m1 - m0 + EPS);
        }
    }
    __syncthreads();

    const float mn  = sh_mn;
    const float inv = sh_inv;

    // ---- compute s, r for own 4 elems into smem ----
    float4 s4, r4;
    s4.x = fminf(fmaxf(v.x * inv - mn * inv - 1.0f, -1.0f + EPS), 1.0f - EPS);
    s4.y = fminf(fmaxf(v.y * inv - mn * inv - 1.0f, -1.0f + EPS), 1.0f - EPS);
    s4.z = fminf(fmaxf(v.z * inv - mn * inv - 1.0f, -1.0f + EPS), 1.0f - EPS);
    s4.w = fminf(fmaxf(v.w * inv - mn * inv - 1.0f, -1.0f + EPS), 1.0f - EPS);
    r4.x = sqrtf(fmaxf(1.0f - s4.x * s4.x, 0.0f));
    r4.y = sqrtf(fmaxf(1.0f - s4.y * s4.y, 0.0f));
    r4.z = sqrtf(fmaxf(1.0f - s4.z * s4.z, 0.0f));
    r4.w = sqrtf(fmaxf(1.0f - s4.w * s4.w, 0.0f));

    reinterpret_cast<float4*>(s_s)[t] = s4;
    reinterpret_cast<float4*>(s_r)[t] = r4;
    __syncthreads();

    // ---- 8 output rows: si/ri broadcast from smem, j-segment in regs ----
    float si[ROWS_PER_BLK], ri[ROWS_PER_BLK];
    #pragma unroll
    for (int k = 0; k < ROWS_PER_BLK; k++) {
        si[k] = s_s[i0 + k];
        ri[k] = s_r[i0 + k];
    }

    float* base = out + (size_t)b * L * L + (size_t)i0 * L;

    #pragma unroll
    for (int k = 0; k < ROWS_PER_BLK; k++) {
        float4 o;
        o.x = si[k] * s4.x - ri[k] * r4.x;
        o.y = si[k] * s4.y - ri[k] * r4.y;
        o.z = si[k] * s4.z - ri[k] * r4.z;
        o.w = si[k] * s4.w - ri[k] * r4.w;
        __stcs(reinterpret_cast<float4*>(base + (size_t)k * L) + t, o);
    }
}

extern "C" void kernel_launch(void* const* d_in, const int* in_sizes, int n_in,
                              void* d_out, int out_size) {
    const float* x = (const float*)d_in[0];
    float* out = (float*)d_out;

    dim3 grid(L / ROWS_PER_BLK, B);
    gaf_fused_kernel<<<grid, THREADS>>>(x, out);
}

// round 4
// speedup vs baseline: 1.2361x; 1.0486x over previous
#include <cuda_runtime.h>

#define B 16
#define L 2048
#define EPS 1e-8f
#define ROWS_PER_BLK 16
#define THREADS 512

// Fused GAF: out[b][i][j] = s_i*s_j - r_i*r_j, s = clipped minmax scale of x,
// r = sqrt(1-s^2)  (cos/sin of arccos -> no trig needed).
// One block = 16 consecutive i-rows of one batch. Each thread keeps its own
// 4 j-values in registers; only the 16 (si,ri) pairs go through (tiny) smem.
__global__ void __launch_bounds__(THREADS) gaf_fused_kernel(
    const float* __restrict__ x, float* __restrict__ out) {
    const int b  = blockIdx.y;
    const int i0 = blockIdx.x * ROWS_PER_BLK;
    const int t  = threadIdx.x;
    const int lane = t & 31;
    const int wid  = t >> 5;                 // 16 warps

    __shared__ float red_min[16], red_max[16];
    __shared__ float sh_mn, sh_inv;
    __shared__ float sh_si[ROWS_PER_BLK], sh_ri[ROWS_PER_BLK];

    // ---- load x row: 512 threads x float4 = 2048 elems ----
    const float4 v = reinterpret_cast<const float4*>(x + b * L)[t];

    float vmin = fminf(fminf(v.x, v.y), fminf(v.z, v.w));
    float vmax = fmaxf(fmaxf(v.x, v.y), fmaxf(v.z, v.w));
    #pragma unroll
    for (int o = 16; o > 0; o >>= 1) {
        vmin = fminf(vmin, __shfl_xor_sync(0xffffffffu, vmin, o));
        vmax = fmaxf(vmax, __shfl_xor_sync(0xffffffffu, vmax, o));
    }
    if (lane == 0) { red_min[wid] = vmin; red_max[wid] = vmax; }
    __syncthreads();

    if (wid == 0) {
        float m0 = (lane < 16) ? red_min[lane] :  3.4e38f;
        float m1 = (lane < 16) ? red_max[lane] : -3.4e38f;
        #pragma unroll
        for (int o = 8; o > 0; o >>= 1) {
            m0 = fminf(m0, __shfl_xor_sync(0xffffffffu, m0, o));
            m1 = fmaxf(m1, __shfl_xor_sync(0xffffffffu, m1, o));
        }
        if (lane == 0) {
            sh_mn  = m0;
            sh_inv = 2.0f / (m1 - m0 + EPS);
        }
    }
    __syncthreads();

    const float mn  = sh_mn;
    const float inv = sh_inv;

    // ---- own 4 j-values in registers ----
    float4 s4, r4;
    s4.x = fminf(fmaxf((v.x - mn) * inv - 1.0f, -1.0f + EPS), 1.0f - EPS);
    s4.y = fminf(fmaxf((v.y - mn) * inv - 1.0f, -1.0f + EPS), 1.0f - EPS);
    s4.z = fminf(fmaxf((v.z - mn) * inv - 1.0f, -1.0f + EPS), 1.0f - EPS);
    s4.w = fminf(fmaxf((v.w - mn) * inv - 1.0f, -1.0f + EPS), 1.0f - EPS);
    r4.x = sqrtf(fmaxf(1.0f - s4.x * s4.x, 0.0f));
    r4.y = sqrtf(fmaxf(1.0f - s4.y * s4.y, 0.0f));
    r4.z = sqrtf(fmaxf(1.0f - s4.z * s4.z, 0.0f));
    r4.w = sqrtf(fmaxf(1.0f - s4.w * s4.w, 0.0f));

    // ---- publish the 16 (si,ri) pairs this block needs ----
    // element i0+e is owned by thread (i0+e)>>2, component e&3
    const int rel = t * 4 - i0;               // index of v.x within [0,16)?
    if (rel >= 0 && rel < ROWS_PER_BLK) {
        sh_si[rel + 0] = s4.x;  sh_ri[rel + 0] = r4.x;
        sh_si[rel + 1] = s4.y;  sh_ri[rel + 1] = r4.y;
        sh_si[rel + 2] = s4.z;  sh_ri[rel + 2] = r4.z;
        sh_si[rel + 3] = s4.w;  sh_ri[rel + 3] = r4.w;
    }
    __syncthreads();

    float* base = out + (size_t)b * L * L + (size_t)i0 * L;

    // ---- 16 rows in two unrolled halves (bounds register pressure) ----
    #pragma unroll
    for (int h = 0; h < 2; h++) {
        float si[8], ri[8];
        #pragma unroll
        for (int k = 0; k < 8; k++) {
            si[k] = sh_si[h * 8 + k];
            ri[k] = sh_ri[h * 8 + k];
        }
        #pragma unroll
        for (int k = 0; k < 8; k++) {
            float4 o;
            o.x = si[k] * s4.x - ri[k] * r4.x;
            o.y = si[k] * s4.y - ri[k] * r4.y;
            o.z = si[k] * s4.z - ri[k] * r4.z;
            o.w = si[k] * s4.w - ri[k] * r4.w;
            __stcs(reinterpret_cast<float4*>(base + (size_t)(h * 8 + k) * L) + t, o);
        }
    }
}

extern "C" void kernel_launch(void* const* d_in, const int* in_sizes, int n_in,
                              void* d_out, int out_size) {
    const float* x = (const float*)d_in[0];
    float* out = (float*)d_out;

    dim3 grid(L / ROWS_PER_BLK, B);
    gaf_fused_kernel<<<grid, THREADS>>>(x, out);
}